// round 14
// baseline (speedup 1.0000x reference)
#include <cuda_runtime.h>
#include <math_constants.h>

#define B_DIM 8
#define S_DIM 4096
#define H_DIM 1024
#define N_SPANS 100
#define TOTAL_SPANS (B_DIM * N_SPANS)     // 800
#define MAX_LEN 64
#define CHUNK 16
#define N_CHUNKS 4
#define TOTAL_ITEMS (TOTAL_SPANS * N_CHUNKS)  // 3200

#define W (H_DIM / 4)   // 256 float4 lanes per row
#define GRID_CTAS (148 * 6)   // persistent: 6 CTAs/SM on 148 SMs

__device__ __forceinline__ float4 fmax4(float4 a, float4 b) {
    float4 r;
    r.x = fmaxf(a.x, b.x);
    r.y = fmaxf(a.y, b.y);
    r.z = fmaxf(a.z, b.z);
    r.w = fmaxf(a.w, b.w);
    return r;
}

// Order-preserving float atomic max (stored value remains a normal float):
//  - nonneg floats: int ordering == float ordering  -> atomicMax(int)
//  - negative floats: unsigned ordering is reversed -> atomicMin(uint)
// Mixed-sign races resolve correctly in both orders.
// Init pattern 0xFFFFFFFF is an identity: as int = -1 (any v>=0 wins),
// as uint = UINT_MAX (any v<0 wins). Every column gets >=1 update (len>=1).
__device__ __forceinline__ void atomicMaxFloat(float* addr, float v) {
    int vi = __float_as_int(v);
    if (vi >= 0) {
        atomicMax((int*)addr, vi);
    } else {
        atomicMin((unsigned int*)addr, (unsigned int)vi);
    }
}

__global__ __launch_bounds__(W, 6)
void maxpool_persistent_kernel(const float* __restrict__ ctx,
                               const int* __restrict__ begins,
                               const int* __restrict__ lens,
                               float* __restrict__ out) {
    // All span metadata lives in smem: 800 * 8B = 6.4 KB.
    __shared__ int s_begin[TOTAL_SPANS];
    __shared__ int s_len[TOTAL_SPANS];

    const int tid = threadIdx.x;

    // Cooperative metadata load: coalesced, overlapped (independent LDGs),
    // L2-hit for every CTA after the first wave touches it.
    #pragma unroll
    for (int i = tid; i < TOTAL_SPANS; i += W) {
        s_begin[i] = __ldg(&begins[i]);
        s_len[i]   = __ldg(&lens[i]);
    }
    __syncthreads();

    // Grid-stride over chunk work-items. Metadata access is now a ~29-cycle
    // LDS instead of a ~600-cycle dependent LDG per item.
    for (int item = blockIdx.x; item < TOTAL_ITEMS; item += GRID_CTAS) {
        const int span  = item >> 2;
        const int chunk = item & 3;
        const int b     = span / N_SPANS;

        int len = s_len[span];
        len = len < 1 ? 1 : len;

        // Balanced dynamic chunking (same as R12): nchunks = ceil(len/16),
        // rows split near-equally so sibling items finish within +-1 row.
        const int nchunks = (len + CHUNK - 1) >> 4;   // 1..4
        if (chunk >= nchunks) continue;               // inactive: ~free now
        const int q = len / nchunks;
        const int r = len - q * nchunks;
        const int rows  = q + (chunk < r ? 1 : 0);    // 8..16 for len>=8
        const int start = chunk * q + min(chunk, r);

        const float4* base = (const float4*)(ctx + (long long)b * S_DIM * H_DIM
                                 + (long long)(s_begin[span] + start) * H_DIM) + tid;

        const float NEG = -CUDART_INF_F;
        float4 m0 = make_float4(NEG, NEG, NEG, NEG);
        float4 m1 = m0, m2 = m0, m3 = m0;

        int p = 0;
        // 8 independent outstanding 16B loads per thread per round (MLP = 8)
        for (; p + 8 <= rows; p += 8) {
            float4 v0 = __ldg(base + (p + 0) * W);
            float4 v1 = __ldg(base + (p + 1) * W);
            float4 v2 = __ldg(base + (p + 2) * W);
            float4 v3 = __ldg(base + (p + 3) * W);
            float4 v4 = __ldg(base + (p + 4) * W);
            float4 v5 = __ldg(base + (p + 5) * W);
            float4 v6 = __ldg(base + (p + 6) * W);
            float4 v7 = __ldg(base + (p + 7) * W);
            m0 = fmax4(m0, fmax4(v0, v4));
            m1 = fmax4(m1, fmax4(v1, v5));
            m2 = fmax4(m2, fmax4(v2, v6));
            m3 = fmax4(m3, fmax4(v3, v7));
        }
        if (p + 4 <= rows) {
            float4 v0 = __ldg(base + (p + 0) * W);
            float4 v1 = __ldg(base + (p + 1) * W);
            float4 v2 = __ldg(base + (p + 2) * W);
            float4 v3 = __ldg(base + (p + 3) * W);
            m0 = fmax4(m0, v0);
            m1 = fmax4(m1, v1);
            m2 = fmax4(m2, v2);
            m3 = fmax4(m3, v3);
            p += 4;
        }
        for (; p < rows; p++) {
            m0 = fmax4(m0, __ldg(base + p * W));
        }

        m0 = fmax4(m0, m1);
        m2 = fmax4(m2, m3);
        m0 = fmax4(m0, m2);

        float* o = out + (long long)span * H_DIM + tid * 4;
        atomicMaxFloat(o + 0, m0.x);
        atomicMaxFloat(o + 1, m0.y);
        atomicMaxFloat(o + 2, m0.z);
        atomicMaxFloat(o + 3, m0.w);
    }
}

extern "C" void kernel_launch(void* const* d_in, const int* in_sizes, int n_in,
                              void* d_out, int out_size) {
    const float* ctx    = (const float*)d_in[0];   // [B, S, H] float32
    const int*   begins = (const int*)d_in[1];     // [B, N_SPANS] int32
    const int*   lens   = (const int*)d_in[2];     // [B, N_SPANS] int32
    float* out = (float*)d_out;                    // [B, N_SPANS, H] float32

    // 0xFFFFFFFF is the identity element for atomicMaxFloat above.
    cudaMemsetAsync(out, 0xFF, (size_t)TOTAL_SPANS * H_DIM * sizeof(float));

    maxpool_persistent_kernel<<<GRID_CTAS, W>>>(ctx, begins, lens, out);
}

// round 15
// speedup vs baseline: 1.2467x; 1.2467x over previous
#include <cuda_runtime.h>
#include <math_constants.h>

#define B_DIM 8
#define S_DIM 4096
#define H_DIM 1024
#define N_SPANS 100
#define TOTAL_SPANS (B_DIM * N_SPANS)     // 800
#define MAX_LEN 64

#define W (H_DIM / 4)        // 256 float4 lanes per row
#define NTHREADS (2 * W)     // 512: 2 row-groups x 256 column lanes

__device__ __forceinline__ float4 fmax4(float4 a, float4 b) {
    float4 r;
    r.x = fmaxf(a.x, b.x);
    r.y = fmaxf(a.y, b.y);
    r.z = fmaxf(a.z, b.z);
    r.w = fmaxf(a.w, b.w);
    return r;
}

__global__ __launch_bounds__(NTHREADS, 3)
void maxpool_span_kernel(const float* __restrict__ ctx,
                         const int* __restrict__ begins,
                         const int* __restrict__ lens,
                         float* __restrict__ out) {
    // Group 1's partial maxima; 256 x float4 = 4KB
    __shared__ float4 s_part[W];

    const int span = blockIdx.x;             // 0 .. 799
    const int b    = span / N_SPANS;

    const int tid = threadIdx.x;
    const int col = tid & (W - 1);           // 0..255  (float4 column)
    const int grp = tid >> 8;                // 0 or 1  (row half)

    // Both metadata loads issue concurrently; same address across the CTA -> broadcast.
    const int begin = __ldg(&begins[span]);
    int len = __ldg(&lens[span]);
    len = len < 1 ? 1 : len;

    // Balanced 2-way split: group0 gets ceil(len/2), group1 gets floor(len/2).
    const int half_hi = (len + 1) >> 1;          // 1..32
    const int rows  = grp ? (len >> 1) : half_hi; // group1 may be 0 (len==1)
    const int start = grp ? half_hi : 0;

    const float4* base = (const float4*)(ctx + (long long)b * S_DIM * H_DIM
                             + (long long)(begin + start) * H_DIM) + col;

    const float NEG = -CUDART_INF_F;
    float4 m0 = make_float4(NEG, NEG, NEG, NEG);
    float4 m1 = m0, m2 = m0, m3 = m0;

    int p = 0;
    // 8 independent outstanding 16B loads per thread per round (MLP = 8)
    for (; p + 8 <= rows; p += 8) {
        float4 v0 = __ldg(base + (p + 0) * W);
        float4 v1 = __ldg(base + (p + 1) * W);
        float4 v2 = __ldg(base + (p + 2) * W);
        float4 v3 = __ldg(base + (p + 3) * W);
        float4 v4 = __ldg(base + (p + 4) * W);
        float4 v5 = __ldg(base + (p + 5) * W);
        float4 v6 = __ldg(base + (p + 6) * W);
        float4 v7 = __ldg(base + (p + 7) * W);
        m0 = fmax4(m0, fmax4(v0, v4));
        m1 = fmax4(m1, fmax4(v1, v5));
        m2 = fmax4(m2, fmax4(v2, v6));
        m3 = fmax4(m3, fmax4(v3, v7));
    }
    if (p + 4 <= rows) {
        float4 v0 = __ldg(base + (p + 0) * W);
        float4 v1 = __ldg(base + (p + 1) * W);
        float4 v2 = __ldg(base + (p + 2) * W);
        float4 v3 = __ldg(base + (p + 3) * W);
        m0 = fmax4(m0, v0);
        m1 = fmax4(m1, v1);
        m2 = fmax4(m2, v2);
        m3 = fmax4(m3, v3);
        p += 4;
    }
    for (; p < rows; p++) {
        m0 = fmax4(m0, __ldg(base + p * W));
    }

    m0 = fmax4(m0, m1);
    m2 = fmax4(m2, m3);
    m0 = fmax4(m0, m2);

    // Combine: group1 publishes its partial (identity -inf if its half was
    // empty — branchless), group0 merges and does ONE plain coalesced store.
    if (grp) {
        s_part[col] = m0;
    }
    __syncthreads();
    if (!grp) {
        m0 = fmax4(m0, s_part[col]);
        float4* o = (float4*)(out + (long long)span * H_DIM) + col;
        *o = m0;
    }
}

extern "C" void kernel_launch(void* const* d_in, const int* in_sizes, int n_in,
                              void* d_out, int out_size) {
    const float* ctx    = (const float*)d_in[0];   // [B, S, H] float32
    const int*   begins = (const int*)d_in[1];     // [B, N_SPANS] int32
    const int*   lens   = (const int*)d_in[2];     // [B, N_SPANS] int32
    float* out = (float*)d_out;                    // [B, N_SPANS, H] float32

    // No init pass, no atomics: each span's CTA produces the final value
    // and writes it with a single plain store.
    maxpool_span_kernel<<<TOTAL_SPANS, NTHREADS>>>(ctx, begins, lens, out);
}